// round 11
// baseline (speedup 1.0000x reference)
#include <cuda_runtime.h>
#include <cuda_bf16.h>

// ---------------------------------------------------------------------------
// MHCLayerAITER fused persistent-CTA kernel.
// out[b,i,c] = sum_j M[i][j]*x[b,j,c] + 2*sig(H_post[i]) * y[b,c]
//   y[b,c]   = bf16(x_agg[b,c]) / rms_b * bf16(w[c])
//   x_agg    = sum_n sig(H_pre[n]) * x[b,n,c]
//   rms_b    = sqrt(mean_c bf16(x_agg)^2 + 1e-6)
//   M        = sinkhorn_knopp(exp(H_res), 3 iters, eps=1e-6)
// B=8192, n=4, C=2048. HBM-bound: 268MB in + 268MB out.
//
// Persistent grid = 592 CTAs (one full wave at 4 CTAs/SM on 148 SMs), each
// looping over ~14 batch rows. This removes per-block launch/drain and the
// cold-start MLP ramp of 8192 short blocks: stores of row i are in flight
// while loads of row i+1 issue. Sinkhorn runs once per block (per-warp
// shuffle butterfly, no smem) before the loop. One barrier per row.
// ---------------------------------------------------------------------------

namespace {
constexpr int kB = 8192;
constexpr int kN = 4;
constexpr int kC = 2048;
constexpr int kThreads = 256;
constexpr int kC4 = kC / 4;            // 512 float4 per stream per row
constexpr int kVec = kC4 / kThreads;   // 2 float4 chunks per thread
constexpr int kGrid = 592;             // 148 SMs x 4 CTAs -> exactly one wave
constexpr float kEps = 1e-6f;
constexpr unsigned kFull = 0xFFFFFFFFu;
}

__global__ __launch_bounds__(kThreads, 4) void mhc_persistent_kernel(
    const float4* __restrict__ x,      // [B, n, C/4]
    const float4* __restrict__ w,      // [C/4]
    const float*  __restrict__ H_pre,  // [4]
    const float*  __restrict__ H_post, // [4]
    const float*  __restrict__ H_res,  // [4,4]
    float4* __restrict__ out) {        // [B, n, C/4]
    const int t = threadIdx.x;
    const int lane = t & 31;
    const int wid = t >> 5;

    __shared__ float s_warp[kThreads / 32];

    // ---- Once per block: per-warp Sinkhorn-Knopp + activations.
    // Lane l (<16) owns P[l/4][l%4]. Row sums via butterfly offsets {1,2},
    // column sums via {4,8}. Lanes 16-31 run with p=exp(0)=1; their
    // butterflies stay in the upper half and never pollute lanes 0-15.
    float pv;
    {
        float h = (lane < 16) ? H_res[lane] : 0.0f;
        float p = expf(h);
#pragma unroll
        for (int it = 0; it < 3; ++it) {
            float s = p;
            s += __shfl_xor_sync(kFull, s, 1);
            s += __shfl_xor_sync(kFull, s, 2);
            p = p / (s + kEps);          // row normalize
            s = p;
            s += __shfl_xor_sync(kFull, s, 4);
            s += __shfl_xor_sync(kFull, s, 8);
            p = p / (s + kEps);          // column normalize
        }
        pv = p;                          // lanes<16: M[lane/4][lane%4]
        if (lane >= 16 && lane < 20)
            pv = 1.0f / (1.0f + expf(-H_pre[lane - 16]));
        else if (lane >= 20 && lane < 24)
            pv = 2.0f / (1.0f + expf(-H_post[lane - 20]));
    }
    const float hp0 = __shfl_sync(kFull, pv, 16);
    const float hp1 = __shfl_sync(kFull, pv, 17);
    const float hp2 = __shfl_sync(kFull, pv, 18);
    const float hp3 = __shfl_sync(kFull, pv, 19);

    // Weight, bf16-rounded once (L1/L2-resident; reused across all rows).
    float wr[kVec * 4];
#pragma unroll
    for (int k = 0; k < kVec; ++k) {
        float4 wv = w[t + k * kThreads];
        wr[k * 4 + 0] = __bfloat162float(__float2bfloat16_rn(wv.x));
        wr[k * 4 + 1] = __bfloat162float(__float2bfloat16_rn(wv.y));
        wr[k * 4 + 2] = __bfloat162float(__float2bfloat16_rn(wv.z));
        wr[k * 4 + 3] = __bfloat162float(__float2bfloat16_rn(wv.w));
    }

    // ---- Persistent loop over batch rows ------------------------------------
    for (int b = blockIdx.x; b < kB; b += kGrid) {
        const size_t base = (size_t)b * (kN * kC4);

        // Front-batched loads: all 4 streams, 8 LDG.128. The previous row's
        // stores are still in flight here — cross-row MLP overlap.
        float xr[kN][kVec * 4];
#pragma unroll
        for (int k = 0; k < kVec; ++k) {
            const int c4 = t + k * kThreads;
#pragma unroll
            for (int n = 0; n < kN; ++n) {
                float4 v = x[base + (size_t)n * kC4 + c4];
                xr[n][k * 4 + 0] = v.x;
                xr[n][k * 4 + 1] = v.y;
                xr[n][k * 4 + 2] = v.z;
                xr[n][k * 4 + 3] = v.w;
            }
        }

        // Aggregate streams; round through bf16; accumulate sum of squares.
        float y[kVec * 4];               // bf16(agg), finished in place below
        float lsum = 0.0f;
#pragma unroll
        for (int e = 0; e < kVec * 4; ++e) {
            float a = hp0 * xr[0][e];
            a = fmaf(hp1, xr[1][e], a);
            a = fmaf(hp2, xr[2][e], a);
            a = fmaf(hp3, xr[3][e], a);
            float ab = __bfloat162float(__float2bfloat16_rn(a));
            y[e] = ab;
            lsum = fmaf(ab, ab, lsum);
        }

        // Block reduction over C=2048 — one barrier per row. All threads
        // redundantly finish the sum (no second barrier). __syncthreads also
        // orders this row's s_warp writes against the next row's.
#pragma unroll
        for (int off = 16; off > 0; off >>= 1)
            lsum += __shfl_xor_sync(kFull, lsum, off);
        if (lane == 0) s_warp[wid] = lsum;
        __syncthreads();
        float ssum = 0.0f;
#pragma unroll
        for (int i = 0; i < kThreads / 32; ++i) ssum += s_warp[i];
        const float rinv = rsqrtf(ssum * (1.0f / (float)kC) + kEps);
        __syncthreads();   // protect s_warp from next iteration's writes

        // Finish y in place.
#pragma unroll
        for (int e = 0; e < kVec * 4; ++e)
            y[e] *= rinv * wr[e];

        // Mix + combine. One M row (+hpost) live at a time via warp shuffle.
#pragma unroll
        for (int i = 0; i < kN; ++i) {
            const float m0 = __shfl_sync(kFull, pv, i * 4 + 0);
            const float m1 = __shfl_sync(kFull, pv, i * 4 + 1);
            const float m2 = __shfl_sync(kFull, pv, i * 4 + 2);
            const float m3 = __shfl_sync(kFull, pv, i * 4 + 3);
            const float hpost_i = __shfl_sync(kFull, pv, 20 + i);
#pragma unroll
            for (int k = 0; k < kVec; ++k) {
                const int c4 = t + k * kThreads;
                float r[4];
#pragma unroll
                for (int q = 0; q < 4; ++q) {
                    const int e = k * 4 + q;
                    float acc = hpost_i * y[e];
                    acc = fmaf(m0, xr[0][e], acc);
                    acc = fmaf(m1, xr[1][e], acc);
                    acc = fmaf(m2, xr[2][e], acc);
                    acc = fmaf(m3, xr[3][e], acc);
                    r[q] = acc;
                }
                float4 o;
                o.x = r[0]; o.y = r[1]; o.z = r[2]; o.w = r[3];
                out[base + (size_t)i * kC4 + c4] = o;
            }
        }
    }
}

// ---------------------------------------------------------------------------
// Launch. Inputs (metadata order): x, rmsnorm_weight, H_pre, H_post, H_res.
// Single graph node, persistent grid.
// ---------------------------------------------------------------------------
extern "C" void kernel_launch(void* const* d_in, const int* in_sizes, int n_in,
                              void* d_out, int out_size) {
    const float* x      = (const float*)d_in[0];
    const float* w      = (const float*)d_in[1];
    const float* H_pre  = (const float*)d_in[2];
    const float* H_post = (const float*)d_in[3];
    const float* H_res  = (const float*)d_in[4];
    float* out = (float*)d_out;

    mhc_persistent_kernel<<<kGrid, kThreads>>>(
        (const float4*)x, (const float4*)w, H_pre, H_post, H_res,
        (float4*)out);
}

// round 12
// speedup vs baseline: 1.2434x; 1.2434x over previous
#include <cuda_runtime.h>
#include <cuda_bf16.h>

// ---------------------------------------------------------------------------
// MHCLayerAITER fused single-kernel, barrier-free prologue, L2-only x loads.
// out[b,i,c] = sum_j M[i][j]*x[b,j,c] + 2*sig(H_post[i]) * y[b,c]
//   y[b,c]   = bf16(x_agg[b,c]) / rms_b * bf16(w[c])
//   x_agg    = sum_n sig(H_pre[n]) * x[b,n,c]
//   rms_b    = sqrt(mean_c bf16(x_agg)^2 + 1e-6)
//   M        = sinkhorn_knopp(exp(H_res), 3 iters, eps=1e-6)
// B=8192, n=4, C=2048. HBM-bound: 268MB in + 268MB out.
//
// Shape = R10 (best fused: grid 8192, 256 thr, kVec=2, 64-reg cap, per-warp
// redundant Sinkhorn hidden behind the 8 front-batched LDGs, single barrier).
// R11's persistent grid regressed (per-row barriers drain MLP) and is
// reverted. Single delta this round: x is loaded with __ldcg — read-once
// data skips L1 allocation, halving L1tex work on the 256MB input stream.
// ---------------------------------------------------------------------------

namespace {
constexpr int kB = 8192;
constexpr int kN = 4;
constexpr int kC = 2048;
constexpr int kThreads = 256;
constexpr int kC4 = kC / 4;            // 512 float4 per stream per row
constexpr int kVec = kC4 / kThreads;   // 2 float4 chunks per thread
constexpr float kEps = 1e-6f;
constexpr unsigned kFull = 0xFFFFFFFFu;
}

__global__ __launch_bounds__(kThreads, 4) void mhc_fused_kernel(
    const float4* __restrict__ x,      // [B, n, C/4]
    const float4* __restrict__ w,      // [C/4]
    const float*  __restrict__ H_pre,  // [4]
    const float*  __restrict__ H_post, // [4]
    const float*  __restrict__ H_res,  // [4,4]
    float4* __restrict__ out) {        // [B, n, C/4]
    const int b = blockIdx.x;
    const int t = threadIdx.x;
    const int lane = t & 31;
    const int wid = t >> 5;

    __shared__ float s_warp[kThreads / 32];

    const size_t base = (size_t)b * (kN * kC4);

    // ---- Phase 1 (FIRST): front-batched loads — all 4 streams, 8 LDG.128.
    //      __ldcg: L2-only, no L1 allocation (x is consumed exactly once).
    float xr[kN][kVec * 4];
#pragma unroll
    for (int k = 0; k < kVec; ++k) {
        const int c4 = t + k * kThreads;
#pragma unroll
        for (int n = 0; n < kN; ++n) {
            float4 v = __ldcg(&x[base + (size_t)n * kC4 + c4]);
            xr[n][k * 4 + 0] = v.x;
            xr[n][k * 4 + 1] = v.y;
            xr[n][k * 4 + 2] = v.z;
            xr[n][k * 4 + 3] = v.w;
        }
    }

    // ---- Phase 0 (hidden behind the LDGs): per-warp Sinkhorn + activations.
    // Lane l (<16) owns P[l/4][l%4]. Row sums via butterfly offsets {1,2},
    // column sums via {4,8}. Lanes 16-31 run with p=exp(0)=1; their
    // butterflies stay in the upper half and never pollute lanes 0-15.
    // Every warp computes its own copy -> no barrier, no smem.
    float pv;
    {
        float h = (lane < 16) ? H_res[lane] : 0.0f;
        float p = expf(h);
#pragma unroll
        for (int it = 0; it < 3; ++it) {
            float s = p;
            s += __shfl_xor_sync(kFull, s, 1);
            s += __shfl_xor_sync(kFull, s, 2);
            p = p / (s + kEps);          // row normalize
            s = p;
            s += __shfl_xor_sync(kFull, s, 4);
            s += __shfl_xor_sync(kFull, s, 8);
            p = p / (s + kEps);          // column normalize
        }
        pv = p;                          // lanes<16: M[lane/4][lane%4]
        if (lane >= 16 && lane < 20)
            pv = 1.0f / (1.0f + expf(-H_pre[lane - 16]));
        else if (lane >= 20 && lane < 24)
            pv = 2.0f / (1.0f + expf(-H_post[lane - 20]));
    }

    const float hp0 = __shfl_sync(kFull, pv, 16);
    const float hp1 = __shfl_sync(kFull, pv, 17);
    const float hp2 = __shfl_sync(kFull, pv, 18);
    const float hp3 = __shfl_sync(kFull, pv, 19);

    // ---- Phase 2: aggregate streams; round through bf16; sum of squares ----
    float y[kVec * 4];                   // holds bf16(agg) until finished below
    float lsum = 0.0f;
#pragma unroll
    for (int e = 0; e < kVec * 4; ++e) {
        float a = hp0 * xr[0][e];
        a = fmaf(hp1, xr[1][e], a);
        a = fmaf(hp2, xr[2][e], a);
        a = fmaf(hp3, xr[3][e], a);
        float ab = __bfloat162float(__float2bfloat16_rn(a));
        y[e] = ab;
        lsum = fmaf(ab, ab, lsum);
    }

    // ---- Phase 3: block reduction over C=2048 — ONE barrier ----------------
#pragma unroll
    for (int off = 16; off > 0; off >>= 1)
        lsum += __shfl_xor_sync(kFull, lsum, off);
    if (lane == 0) s_warp[wid] = lsum;
    __syncthreads();
    float ssum = 0.0f;
#pragma unroll
    for (int i = 0; i < kThreads / 32; ++i) ssum += s_warp[i];
    const float rinv = rsqrtf(ssum * (1.0f / (float)kC) + kEps);

    // ---- Phase 4: finish y in place. w loaded now (default caching — it IS
    //      reused across blocks and lives in L1/L2).
#pragma unroll
    for (int k = 0; k < kVec; ++k) {
        float4 wv = w[t + k * kThreads];
        y[k * 4 + 0] *= rinv * __bfloat162float(__float2bfloat16_rn(wv.x));
        y[k * 4 + 1] *= rinv * __bfloat162float(__float2bfloat16_rn(wv.y));
        y[k * 4 + 2] *= rinv * __bfloat162float(__float2bfloat16_rn(wv.z));
        y[k * 4 + 3] *= rinv * __bfloat162float(__float2bfloat16_rn(wv.w));
    }

    // ---- Phase 5: mix + combine. One M row (+hpost) live at a time,
    //      fetched by warp shuffle from pv. ---------------------------------
#pragma unroll
    for (int i = 0; i < kN; ++i) {
        const float m0 = __shfl_sync(kFull, pv, i * 4 + 0);
        const float m1 = __shfl_sync(kFull, pv, i * 4 + 1);
        const float m2 = __shfl_sync(kFull, pv, i * 4 + 2);
        const float m3 = __shfl_sync(kFull, pv, i * 4 + 3);
        const float hpost_i = __shfl_sync(kFull, pv, 20 + i);
#pragma unroll
        for (int k = 0; k < kVec; ++k) {
            const int c4 = t + k * kThreads;
            float r[4];
#pragma unroll
            for (int q = 0; q < 4; ++q) {
                const int e = k * 4 + q;
                float acc = hpost_i * y[e];
                acc = fmaf(m0, xr[0][e], acc);
                acc = fmaf(m1, xr[1][e], acc);
                acc = fmaf(m2, xr[2][e], acc);
                acc = fmaf(m3, xr[3][e], acc);
                r[q] = acc;
            }
            float4 o;
            o.x = r[0]; o.y = r[1]; o.z = r[2]; o.w = r[3];
            out[base + (size_t)i * kC4 + c4] = o;
        }
    }
}

// ---------------------------------------------------------------------------
// Launch. Inputs (metadata order): x, rmsnorm_weight, H_pre, H_post, H_res.
// Single graph node.
// ---------------------------------------------------------------------------
extern "C" void kernel_launch(void* const* d_in, const int* in_sizes, int n_in,
                              void* d_out, int out_size) {
    const float* x      = (const float*)d_in[0];
    const float* w      = (const float*)d_in[1];
    const float* H_pre  = (const float*)d_in[2];
    const float* H_post = (const float*)d_in[3];
    const float* H_res  = (const float*)d_in[4];
    float* out = (float*)d_out;

    mhc_fused_kernel<<<kB, kThreads>>>(
        (const float4*)x, (const float4*)w, H_pre, H_post, H_res,
        (float4*)out);
}